// round 1
// baseline (speedup 1.0000x reference)
#include <cuda_runtime.h>
#include <math.h>

// Problem constants
#define BB   64      // batch
#define SS   512     // sequence
#define DIN  64      // input dim
#define HH   512     // hidden
#define NLAY 4       // layers
#define DOUT 64

#define NB   128     // blocks (32 per layer)
#define NT   256     // threads per block
#define KT   64      // K tile
#define PAD  68      // smem row pitch (floats), 16B-aligned, conflict-light

#define SMEM_BYTES ((512*PAD + 64*PAD + 32) * 4)   // phase-3 dominates: 156800 B

// Persistent state (scratch) — device globals per harness rules
__device__ float g_h[NLAY][2][BB][HH];   // h ring by wave parity
__device__ float g_c[NLAY][BB][HH];      // cell state (block-local access)
__device__ float g_h3[(size_t)BB * SS * HH];  // layer-3 h for all t (64 MB)
__device__ unsigned int g_arrive = 0;    // barrier: cumulative arrivals
__device__ unsigned int g_gen    = 0;    // barrier: generation counter

__device__ __forceinline__ void gridbar(unsigned int& lgen) {
    __syncthreads();
    __threadfence();
    if (threadIdx.x == 0) {
        unsigned int old = atomicAdd(&g_arrive, 1u);
        if (((old + 1u) % NB) == 0u) {
            atomicAdd(&g_gen, 1u);   // release
        } else {
            while (*((volatile unsigned int*)&g_gen) < lgen + 1u) {
                __nanosleep(64);
            }
        }
    }
    lgen += 1u;
    __syncthreads();
    __threadfence();
}

__global__ void __launch_bounds__(NT, 1) lstm_persistent_kernel(
    const float* __restrict__ x,
    const float* __restrict__ W0, const float* __restrict__ b0,
    const float* __restrict__ W1, const float* __restrict__ b1,
    const float* __restrict__ W2, const float* __restrict__ b2,
    const float* __restrict__ W3, const float* __restrict__ b3,
    const float* __restrict__ lng, const float* __restrict__ lnb,
    const float* __restrict__ Wo,  const float* __restrict__ bo,
    float* __restrict__ out)
{
    extern __shared__ float sm[];
    const int tid = threadIdx.x;
    const int bx  = blockIdx.x;

    // Barrier generation base: stable at kernel entry (monotonic across launches)
    unsigned int lgen = *((volatile unsigned int*)&g_gen);

    // ---------------- Phase 0: zero recurrent state (must re-zero every launch) ----
    {
        float* p1 = &g_h[0][0][0][0]; const int n1 = NLAY * 2 * BB * HH;
        float* p2 = &g_c[0][0][0];    const int n2 = NLAY * BB * HH;
        for (int i = bx * NT + tid; i < n1; i += NB * NT) p1[i] = 0.0f;
        for (int i = bx * NT + tid; i < n2; i += NB * NT) p2[i] = 0.0f;
    }
    gridbar(lgen);

    // ---------------- Phase 1: skewed-wavefront LSTM ----------------
    const int layer = bx >> 5;          // 0..3
    const int blk   = bx & 31;          // 0..31
    const float* Wl = (layer == 0) ? W0 : (layer == 1) ? W1 : (layer == 2) ? W2 : W3;
    const float* bl = (layer == 0) ? b0 : (layer == 1) ? b1 : (layer == 2) ? b2 : b3;
    const int fanin = (layer == 0) ? (DIN + HH) : (2 * HH);
    const int Kin   = (layer == 0) ? DIN : HH;
    const int u0    = blk * 16;

    const int tc  = tid & 15;           // 0..15 : hidden-unit offset within tile
    const int tr  = tid >> 4;           // 0..15 : 4 batch rows each
    const int lkk = tid & 63;           // loader: k within chunk
    const int lr0 = tid >> 6;           // loader: 0..3

    float* As = sm;                     // [KT][PAD]  A tile (k-major, rows transposed in)
    float* Ws = sm + KT * PAD;          // [KT][PAD]  W tile, entry (k, u'*4+gate)

    for (int w = 0; w < SS + NLAY - 1; ++w) {
        const int t = w - layer;
        if (t >= 0 && t < SS) {
            const int pprev = (w - 1) & 1;
            const int pcur  = w & 1;

            float acc[4][4];
            #pragma unroll
            for (int g = 0; g < 4; ++g) {
                const float bv = bl[g * HH + u0 + tc];
                #pragma unroll
                for (int r = 0; r < 4; ++r) acc[r][g] = bv;
            }

            const int nch = fanin / KT;
            for (int ch = 0; ch < nch; ++ch) {
                const int k = ch * KT + lkk;
                // ---- stage A tile (transpose to [k][b]); cross-SM h via __ldcg ----
                if (k < Kin) {
                    if (layer == 0) {
                        #pragma unroll
                        for (int p = 0; p < 16; ++p) {
                            const int b = p * 4 + lr0;
                            As[lkk * PAD + b] = __ldg(&x[((size_t)b * SS + t) * DIN + k]);
                        }
                    } else {
                        const float* src = &g_h[layer - 1][pprev][0][0];
                        #pragma unroll
                        for (int p = 0; p < 16; ++p) {
                            const int b = p * 4 + lr0;
                            As[lkk * PAD + b] = __ldcg(&src[b * HH + k]);
                        }
                    }
                } else {
                    const float* src = &g_h[layer][pprev][0][0];
                    const int koff = k - Kin;
                    #pragma unroll
                    for (int p = 0; p < 16; ++p) {
                        const int b = p * 4 + lr0;
                        As[lkk * PAD + b] = __ldcg(&src[b * HH + koff]);
                    }
                }
                // ---- stage W tile: entry (k, u', gate) at [k][u'*4+gate] ----
                #pragma unroll
                for (int p = 0; p < 16; ++p) {
                    const int jc   = p * 4 + lr0;      // 0..63
                    const int gate = jc >> 4;
                    const int up   = jc & 15;
                    Ws[lkk * PAD + up * 4 + gate] =
                        Wl[(size_t)(gate * HH + u0 + up) * fanin + k];
                }
                __syncthreads();

                #pragma unroll 16
                for (int kk = 0; kk < KT; ++kk) {
                    const float4 a  = *(const float4*)(As + kk * PAD + tr * 4);
                    const float4 wv = *(const float4*)(Ws + kk * PAD + tc * 4);
                    acc[0][0] += a.x * wv.x; acc[0][1] += a.x * wv.y;
                    acc[0][2] += a.x * wv.z; acc[0][3] += a.x * wv.w;
                    acc[1][0] += a.y * wv.x; acc[1][1] += a.y * wv.y;
                    acc[1][2] += a.y * wv.z; acc[1][3] += a.y * wv.w;
                    acc[2][0] += a.z * wv.x; acc[2][1] += a.z * wv.y;
                    acc[2][2] += a.z * wv.z; acc[2][3] += a.z * wv.w;
                    acc[3][0] += a.w * wv.x; acc[3][1] += a.w * wv.y;
                    acc[3][2] += a.w * wv.z; acc[3][3] += a.w * wv.w;
                }
                __syncthreads();
            }

            // ---- LSTM cell update (thread-local: owns (b, u) pairs) ----
            #pragma unroll
            for (int r = 0; r < 4; ++r) {
                const int b = tr * 4 + r;
                const int u = u0 + tc;
                const float zi = acc[r][0], zf = acc[r][1], zg = acc[r][2], zo = acc[r][3];
                const float si = 1.0f / (1.0f + __expf(-zi));
                const float sf = 1.0f / (1.0f + __expf(-zf));
                const float so = 1.0f / (1.0f + __expf(-zo));
                const float tg = tanhf(zg);
                const float c  = sf * g_c[layer][b][u] + si * tg;
                g_c[layer][b][u] = c;
                const float h = so * tanhf(c);
                g_h[layer][pcur][b][u] = h;
                if (layer == 3) g_h3[((size_t)b * SS + t) * HH + u] = h;
            }
        }
        gridbar(lgen);
    }

    // ---------------- Phase 2: LayerNorm + output projection ----------------
    float* As3 = sm;                         // [512][PAD] normalized h, k-major
    float* Ws3 = sm + 512 * PAD;             // [64][PAD]  Wo tile
    float* red = sm + 512 * PAD + 64 * PAD;  // reduce scratch (18 floats)
    const int lane = tid & 31, wrp = tid >> 5;

    for (int i = 0; i < 4; ++i) {
        const int base_row = bx * 256 + i * 64;   // 128 blocks * 4 * 64 = 32768 rows

        // LN 64 rows into As3 (transposed [k][row])
        for (int rr = 0; rr < 64; ++rr) {
            const size_t row = (size_t)base_row + rr;
            const float v0 = __ldcg(&g_h3[row * HH + tid]);
            const float v1 = __ldcg(&g_h3[row * HH + tid + 256]);
            float s = v0 + v1, s2 = v0 * v0 + v1 * v1;
            #pragma unroll
            for (int off = 16; off > 0; off >>= 1) {
                s  += __shfl_down_sync(0xffffffffu, s,  off);
                s2 += __shfl_down_sync(0xffffffffu, s2, off);
            }
            if (lane == 0) { red[wrp] = s; red[8 + wrp] = s2; }
            __syncthreads();
            if (tid == 0) {
                float S1 = 0.f, S2 = 0.f;
                for (int j = 0; j < 8; ++j) { S1 += red[j]; S2 += red[8 + j]; }
                const float mu  = S1 * (1.0f / 512.0f);
                const float var = S2 * (1.0f / 512.0f) - mu * mu;
                red[16] = mu;
                red[17] = rsqrtf(var + 1e-5f);
            }
            __syncthreads();
            const float mu = red[16], rstd = red[17];
            As3[tid * PAD + rr]         = (v0 - mu) * rstd * lng[tid]       + lnb[tid];
            As3[(tid + 256) * PAD + rr] = (v1 - mu) * rstd * lng[tid + 256] + lnb[tid + 256];
            __syncthreads();
        }

        // GEMM: [64 rows x 64 dout], K = 512
        float acc[4][4];
        #pragma unroll
        for (int r = 0; r < 4; ++r)
            #pragma unroll
            for (int g = 0; g < 4; ++g) acc[r][g] = 0.0f;

        for (int ch = 0; ch < 8; ++ch) {
            #pragma unroll
            for (int p = 0; p < 16; ++p) {
                const int jc = p * 4 + lr0;      // d index 0..63
                Ws3[lkk * PAD + (jc & 15) * 4 + (jc >> 4)] =
                    Wo[(size_t)jc * HH + ch * 64 + lkk];
            }
            __syncthreads();
            #pragma unroll 16
            for (int kk = 0; kk < 64; ++kk) {
                const float4 a  = *(const float4*)(As3 + (ch * 64 + kk) * PAD + tr * 4);
                const float4 wv = *(const float4*)(Ws3 + kk * PAD + tc * 4);
                acc[0][0] += a.x * wv.x; acc[0][1] += a.x * wv.y;
                acc[0][2] += a.x * wv.z; acc[0][3] += a.x * wv.w;
                acc[1][0] += a.y * wv.x; acc[1][1] += a.y * wv.y;
                acc[1][2] += a.y * wv.z; acc[1][3] += a.y * wv.w;
                acc[2][0] += a.z * wv.x; acc[2][1] += a.z * wv.y;
                acc[2][2] += a.z * wv.z; acc[2][3] += a.z * wv.w;
                acc[3][0] += a.w * wv.x; acc[3][1] += a.w * wv.y;
                acc[3][2] += a.w * wv.z; acc[3][3] += a.w * wv.w;
            }
            __syncthreads();
        }

        #pragma unroll
        for (int r = 0; r < 4; ++r) {
            const size_t row = (size_t)base_row + tr * 4 + r;
            #pragma unroll
            for (int g = 0; g < 4; ++g) {
                const int d = g * 16 + tc;
                out[row * DOUT + d] = acc[r][g] + bo[d];
            }
        }
        __syncthreads();
    }
}

extern "C" void kernel_launch(void* const* d_in, const int* in_sizes, int n_in,
                              void* d_out, int out_size) {
    const float* x   = (const float*)d_in[0];
    const float* W0  = (const float*)d_in[1];
    const float* b0  = (const float*)d_in[2];
    const float* W1  = (const float*)d_in[3];
    const float* b1  = (const float*)d_in[4];
    const float* W2  = (const float*)d_in[5];
    const float* b2  = (const float*)d_in[6];
    const float* W3  = (const float*)d_in[7];
    const float* b3  = (const float*)d_in[8];
    const float* lng = (const float*)d_in[9];
    const float* lnb = (const float*)d_in[10];
    const float* Wo  = (const float*)d_in[11];
    const float* bo  = (const float*)d_in[12];
    float* out = (float*)d_out;

    cudaFuncSetAttribute(lstm_persistent_kernel,
                         cudaFuncAttributeMaxDynamicSharedMemorySize, SMEM_BYTES);
    lstm_persistent_kernel<<<NB, NT, SMEM_BYTES>>>(
        x, W0, b0, W1, b1, W2, b2, W3, b3, lng, lnb, Wo, bo, out);
}

// round 2
// speedup vs baseline: 1.0030x; 1.0030x over previous
#include <cuda_runtime.h>
#include <math.h>

// Problem constants
#define BB   64      // batch
#define SS   512     // sequence
#define DIN  64      // input dim
#define HH   512     // hidden
#define NLAY 4       // layers
#define DOUT 64

#define NB   128     // blocks (32 per layer)
#define NT   256     // threads per block
#define KT   64      // K tile
#define PAD  68      // smem row pitch (floats), 16B-aligned, conflict-light

#define SMEM_BYTES ((512*PAD + 64*PAD + 32) * 4)   // phase-3 dominates: 156800 B

// Persistent state (scratch) — device globals per harness rules
__device__ float g_h[NLAY][2][BB][HH];   // h ring by wave parity
__device__ float g_c[NLAY][BB][HH];      // cell state (block-local access)
__device__ float g_h3[(size_t)BB * SS * HH];  // layer-3 h for all t (64 MB)
__device__ unsigned int g_arrive = 0;    // barrier: cumulative arrivals
__device__ unsigned int g_gen    = 0;    // barrier: generation counter

__device__ __forceinline__ void gridbar(unsigned int& lgen) {
    __syncthreads();
    __threadfence();
    if (threadIdx.x == 0) {
        unsigned int old = atomicAdd(&g_arrive, 1u);
        if (((old + 1u) % NB) == 0u) {
            atomicAdd(&g_gen, 1u);   // release
        } else {
            while (*((volatile unsigned int*)&g_gen) < lgen + 1u) {
                __nanosleep(64);
            }
        }
    }
    lgen += 1u;
    __syncthreads();
    __threadfence();
}

__global__ void __launch_bounds__(NT, 1) lstm_persistent_kernel(
    const float* __restrict__ x,
    const float* __restrict__ W0, const float* __restrict__ b0,
    const float* __restrict__ W1, const float* __restrict__ b1,
    const float* __restrict__ W2, const float* __restrict__ b2,
    const float* __restrict__ W3, const float* __restrict__ b3,
    const float* __restrict__ lng, const float* __restrict__ lnb,
    const float* __restrict__ Wo,  const float* __restrict__ bo,
    float* __restrict__ out)
{
    extern __shared__ float sm[];
    const int tid = threadIdx.x;
    const int bx  = blockIdx.x;

    // Barrier generation base: stable at kernel entry (monotonic across launches)
    unsigned int lgen = *((volatile unsigned int*)&g_gen);

    // ---------------- Phase 0: zero recurrent state (must re-zero every launch) ----
    {
        float* p1 = &g_h[0][0][0][0]; const int n1 = NLAY * 2 * BB * HH;
        float* p2 = &g_c[0][0][0];    const int n2 = NLAY * BB * HH;
        for (int i = bx * NT + tid; i < n1; i += NB * NT) p1[i] = 0.0f;
        for (int i = bx * NT + tid; i < n2; i += NB * NT) p2[i] = 0.0f;
    }
    gridbar(lgen);

    // ---------------- Phase 1: skewed-wavefront LSTM ----------------
    const int layer = bx >> 5;          // 0..3
    const int blk   = bx & 31;          // 0..31
    const float* Wl = (layer == 0) ? W0 : (layer == 1) ? W1 : (layer == 2) ? W2 : W3;
    const float* bl = (layer == 0) ? b0 : (layer == 1) ? b1 : (layer == 2) ? b2 : b3;
    const int fanin = (layer == 0) ? (DIN + HH) : (2 * HH);
    const int Kin   = (layer == 0) ? DIN : HH;
    const int u0    = blk * 16;

    const int tc  = tid & 15;           // 0..15 : hidden-unit offset within tile
    const int tr  = tid >> 4;           // 0..15 : 4 batch rows each
    const int lkk = tid & 63;           // loader: k within chunk
    const int lr0 = tid >> 6;           // loader: 0..3

    float* As = sm;                     // [KT][PAD]  A tile (k-major, rows transposed in)
    float* Ws = sm + KT * PAD;          // [KT][PAD]  W tile, entry (k, u'*4+gate)

    for (int w = 0; w < SS + NLAY - 1; ++w) {
        const int t = w - layer;
        if (t >= 0 && t < SS) {
            const int pprev = (w - 1) & 1;
            const int pcur  = w & 1;

            float acc[4][4];
            #pragma unroll
            for (int g = 0; g < 4; ++g) {
                const float bv = bl[g * HH + u0 + tc];
                #pragma unroll
                for (int r = 0; r < 4; ++r) acc[r][g] = bv;
            }

            const int nch = fanin / KT;
            for (int ch = 0; ch < nch; ++ch) {
                const int k = ch * KT + lkk;
                // ---- stage A tile (transpose to [k][b]); cross-SM h via __ldcg ----
                if (k < Kin) {
                    if (layer == 0) {
                        #pragma unroll
                        for (int p = 0; p < 16; ++p) {
                            const int b = p * 4 + lr0;
                            As[lkk * PAD + b] = __ldg(&x[((size_t)b * SS + t) * DIN + k]);
                        }
                    } else {
                        const float* src = &g_h[layer - 1][pprev][0][0];
                        #pragma unroll
                        for (int p = 0; p < 16; ++p) {
                            const int b = p * 4 + lr0;
                            As[lkk * PAD + b] = __ldcg(&src[b * HH + k]);
                        }
                    }
                } else {
                    const float* src = &g_h[layer][pprev][0][0];
                    const int koff = k - Kin;
                    #pragma unroll
                    for (int p = 0; p < 16; ++p) {
                        const int b = p * 4 + lr0;
                        As[lkk * PAD + b] = __ldcg(&src[b * HH + koff]);
                    }
                }
                // ---- stage W tile: entry (k, u', gate) at [k][u'*4+gate] ----
                #pragma unroll
                for (int p = 0; p < 16; ++p) {
                    const int jc   = p * 4 + lr0;      // 0..63
                    const int gate = jc >> 4;
                    const int up   = jc & 15;
                    Ws[lkk * PAD + up * 4 + gate] =
                        Wl[(size_t)(gate * HH + u0 + up) * fanin + k];
                }
                __syncthreads();

                #pragma unroll 16
                for (int kk = 0; kk < KT; ++kk) {
                    const float4 a  = *(const float4*)(As + kk * PAD + tr * 4);
                    const float4 wv = *(const float4*)(Ws + kk * PAD + tc * 4);
                    acc[0][0] += a.x * wv.x; acc[0][1] += a.x * wv.y;
                    acc[0][2] += a.x * wv.z; acc[0][3] += a.x * wv.w;
                    acc[1][0] += a.y * wv.x; acc[1][1] += a.y * wv.y;
                    acc[1][2] += a.y * wv.z; acc[1][3] += a.y * wv.w;
                    acc[2][0] += a.z * wv.x; acc[2][1] += a.z * wv.y;
                    acc[2][2] += a.z * wv.z; acc[2][3] += a.z * wv.w;
                    acc[3][0] += a.w * wv.x; acc[3][1] += a.w * wv.y;
                    acc[3][2] += a.w * wv.z; acc[3][3] += a.w * wv.w;
                }
                __syncthreads();
            }

            // ---- LSTM cell update (thread-local: owns (b, u) pairs) ----
            #pragma unroll
            for (int r = 0; r < 4; ++r) {
                const int b = tr * 4 + r;
                const int u = u0 + tc;
                const float zi = acc[r][0], zf = acc[r][1], zg = acc[r][2], zo = acc[r][3];
                const float si = 1.0f / (1.0f + __expf(-zi));
                const float sf = 1.0f / (1.0f + __expf(-zf));
                const float so = 1.0f / (1.0f + __expf(-zo));
                const float tg = tanhf(zg);
                const float c  = sf * g_c[layer][b][u] + si * tg;
                g_c[layer][b][u] = c;
                const float h = so * tanhf(c);
                g_h[layer][pcur][b][u] = h;
                if (layer == 3) g_h3[((size_t)b * SS + t) * HH + u] = h;
            }
        }
        gridbar(lgen);
    }

    // ---------------- Phase 2: LayerNorm + output projection ----------------
    float* As3 = sm;                         // [512][PAD] normalized h, k-major
    float* Ws3 = sm + 512 * PAD;             // [64][PAD]  Wo tile
    float* red = sm + 512 * PAD + 64 * PAD;  // reduce scratch (18 floats)
    const int lane = tid & 31, wrp = tid >> 5;

    for (int i = 0; i < 4; ++i) {
        const int base_row = bx * 256 + i * 64;   // 128 blocks * 4 * 64 = 32768 rows

        // LN 64 rows into As3 (transposed [k][row])
        for (int rr = 0; rr < 64; ++rr) {
            const size_t row = (size_t)base_row + rr;
            const float v0 = __ldcg(&g_h3[row * HH + tid]);
            const float v1 = __ldcg(&g_h3[row * HH + tid + 256]);
            float s = v0 + v1, s2 = v0 * v0 + v1 * v1;
            #pragma unroll
            for (int off = 16; off > 0; off >>= 1) {
                s  += __shfl_down_sync(0xffffffffu, s,  off);
                s2 += __shfl_down_sync(0xffffffffu, s2, off);
            }
            if (lane == 0) { red[wrp] = s; red[8 + wrp] = s2; }
            __syncthreads();
            if (tid == 0) {
                float S1 = 0.f, S2 = 0.f;
                for (int j = 0; j < 8; ++j) { S1 += red[j]; S2 += red[8 + j]; }
                const float mu  = S1 * (1.0f / 512.0f);
                const float var = S2 * (1.0f / 512.0f) - mu * mu;
                red[16] = mu;
                red[17] = rsqrtf(var + 1e-5f);
            }
            __syncthreads();
            const float mu = red[16], rstd = red[17];
            As3[tid * PAD + rr]         = (v0 - mu) * rstd * lng[tid]       + lnb[tid];
            As3[(tid + 256) * PAD + rr] = (v1 - mu) * rstd * lng[tid + 256] + lnb[tid + 256];
            __syncthreads();
        }

        // GEMM: [64 rows x 64 dout], K = 512
        float acc[4][4];
        #pragma unroll
        for (int r = 0; r < 4; ++r)
            #pragma unroll
            for (int g = 0; g < 4; ++g) acc[r][g] = 0.0f;

        for (int ch = 0; ch < 8; ++ch) {
            #pragma unroll
            for (int p = 0; p < 16; ++p) {
                const int jc = p * 4 + lr0;      // d index 0..63
                Ws3[lkk * PAD + (jc & 15) * 4 + (jc >> 4)] =
                    Wo[(size_t)jc * HH + ch * 64 + lkk];
            }
            __syncthreads();
            #pragma unroll 16
            for (int kk = 0; kk < 64; ++kk) {
                const float4 a  = *(const float4*)(As3 + (ch * 64 + kk) * PAD + tr * 4);
                const float4 wv = *(const float4*)(Ws3 + kk * PAD + tc * 4);
                acc[0][0] += a.x * wv.x; acc[0][1] += a.x * wv.y;
                acc[0][2] += a.x * wv.z; acc[0][3] += a.x * wv.w;
                acc[1][0] += a.y * wv.x; acc[1][1] += a.y * wv.y;
                acc[1][2] += a.y * wv.z; acc[1][3] += a.y * wv.w;
                acc[2][0] += a.z * wv.x; acc[2][1] += a.z * wv.y;
                acc[2][2] += a.z * wv.z; acc[2][3] += a.z * wv.w;
                acc[3][0] += a.w * wv.x; acc[3][1] += a.w * wv.y;
                acc[3][2] += a.w * wv.z; acc[3][3] += a.w * wv.w;
            }
            __syncthreads();
        }

        #pragma unroll
        for (int r = 0; r < 4; ++r) {
            const size_t row = (size_t)base_row + tr * 4 + r;
            #pragma unroll
            for (int g = 0; g < 4; ++g) {
                const int d = g * 16 + tc;
                out[row * DOUT + d] = acc[r][g] + bo[d];
            }
        }
        __syncthreads();
    }
}

extern "C" void kernel_launch(void* const* d_in, const int* in_sizes, int n_in,
                              void* d_out, int out_size) {
    const float* x   = (const float*)d_in[0];
    const float* W0  = (const float*)d_in[1];
    const float* b0  = (const float*)d_in[2];
    const float* W1  = (const float*)d_in[3];
    const float* b1  = (const float*)d_in[4];
    const float* W2  = (const float*)d_in[5];
    const float* b2  = (const float*)d_in[6];
    const float* W3  = (const float*)d_in[7];
    const float* b3  = (const float*)d_in[8];
    const float* lng = (const float*)d_in[9];
    const float* lnb = (const float*)d_in[10];
    const float* Wo  = (const float*)d_in[11];
    const float* bo  = (const float*)d_in[12];
    float* out = (float*)d_out;

    cudaFuncSetAttribute(lstm_persistent_kernel,
                         cudaFuncAttributeMaxDynamicSharedMemorySize, SMEM_BYTES);
    lstm_persistent_kernel<<<NB, NT, SMEM_BYTES>>>(
        x, W0, b0, W1, b1, W2, b2, W3, b3, lng, lnb, Wo, bo, out);
}

// round 3
// speedup vs baseline: 1.0035x; 1.0005x over previous
#include <cuda_runtime.h>
#include <math.h>

// Problem constants
#define BB   64      // batch
#define SS   512     // sequence
#define DIN  64      // input dim
#define HH   512     // hidden
#define NLAY 4       // layers
#define DOUT 64

#define NB   128     // blocks (32 per layer)
#define NT   256     // threads per block
#define KT   64      // K tile
#define PAD  68      // smem row pitch (floats), 16B-aligned, conflict-light

#define SMEM_BYTES ((512*PAD + 64*PAD + 32) * 4)   // phase-3 dominates: 156800 B

// Persistent state (scratch) — device globals per harness rules
__device__ float g_h[NLAY][2][BB][HH];   // h ring by wave parity
__device__ float g_c[NLAY][BB][HH];      // cell state (block-local access)
__device__ float g_h3[(size_t)BB * SS * HH];  // layer-3 h for all t (64 MB)
__device__ unsigned int g_arrive = 0;    // barrier: cumulative arrivals
__device__ unsigned int g_gen    = 0;    // barrier: generation counter

__device__ __forceinline__ void gridbar(unsigned int& lgen) {
    __syncthreads();
    __threadfence();
    if (threadIdx.x == 0) {
        unsigned int old = atomicAdd(&g_arrive, 1u);
        if (((old + 1u) % NB) == 0u) {
            atomicAdd(&g_gen, 1u);   // release
        } else {
            while (*((volatile unsigned int*)&g_gen) < lgen + 1u) {
                __nanosleep(64);
            }
        }
    }
    lgen += 1u;
    __syncthreads();
    __threadfence();
}

__global__ void __launch_bounds__(NT, 1) lstm_persistent_kernel(
    const float* __restrict__ x,
    const float* __restrict__ W0, const float* __restrict__ b0,
    const float* __restrict__ W1, const float* __restrict__ b1,
    const float* __restrict__ W2, const float* __restrict__ b2,
    const float* __restrict__ W3, const float* __restrict__ b3,
    const float* __restrict__ lng, const float* __restrict__ lnb,
    const float* __restrict__ Wo,  const float* __restrict__ bo,
    float* __restrict__ out)
{
    extern __shared__ float sm[];
    const int tid = threadIdx.x;
    const int bx  = blockIdx.x;

    // Barrier generation base: stable at kernel entry (monotonic across launches)
    unsigned int lgen = *((volatile unsigned int*)&g_gen);

    // ---------------- Phase 0: zero recurrent state (must re-zero every launch) ----
    {
        float* p1 = &g_h[0][0][0][0]; const int n1 = NLAY * 2 * BB * HH;
        float* p2 = &g_c[0][0][0];    const int n2 = NLAY * BB * HH;
        for (int i = bx * NT + tid; i < n1; i += NB * NT) p1[i] = 0.0f;
        for (int i = bx * NT + tid; i < n2; i += NB * NT) p2[i] = 0.0f;
    }
    gridbar(lgen);

    // ---------------- Phase 1: skewed-wavefront LSTM ----------------
    const int layer = bx >> 5;          // 0..3
    const int blk   = bx & 31;          // 0..31
    const float* Wl = (layer == 0) ? W0 : (layer == 1) ? W1 : (layer == 2) ? W2 : W3;
    const float* bl = (layer == 0) ? b0 : (layer == 1) ? b1 : (layer == 2) ? b2 : b3;
    const int fanin = (layer == 0) ? (DIN + HH) : (2 * HH);
    const int Kin   = (layer == 0) ? DIN : HH;
    const int u0    = blk * 16;

    const int tc  = tid & 15;           // 0..15 : hidden-unit offset within tile
    const int tr  = tid >> 4;           // 0..15 : 4 batch rows each
    const int lkk = tid & 63;           // loader: k within chunk
    const int lr0 = tid >> 6;           // loader: 0..3

    float* As = sm;                     // [KT][PAD]  A tile (k-major, rows transposed in)
    float* Ws = sm + KT * PAD;          // [KT][PAD]  W tile, entry (k, u'*4+gate)

    for (int w = 0; w < SS + NLAY - 1; ++w) {
        const int t = w - layer;
        if (t >= 0 && t < SS) {
            const int pprev = (w - 1) & 1;
            const int pcur  = w & 1;

            float acc[4][4];
            #pragma unroll
            for (int g = 0; g < 4; ++g) {
                const float bv = bl[g * HH + u0 + tc];
                #pragma unroll
                for (int r = 0; r < 4; ++r) acc[r][g] = bv;
            }

            const int nch = fanin / KT;
            for (int ch = 0; ch < nch; ++ch) {
                const int k = ch * KT + lkk;
                // ---- stage A tile (transpose to [k][b]); cross-SM h via __ldcg ----
                if (k < Kin) {
                    if (layer == 0) {
                        #pragma unroll
                        for (int p = 0; p < 16; ++p) {
                            const int b = p * 4 + lr0;
                            As[lkk * PAD + b] = __ldg(&x[((size_t)b * SS + t) * DIN + k]);
                        }
                    } else {
                        const float* src = &g_h[layer - 1][pprev][0][0];
                        #pragma unroll
                        for (int p = 0; p < 16; ++p) {
                            const int b = p * 4 + lr0;
                            As[lkk * PAD + b] = __ldcg(&src[b * HH + k]);
                        }
                    }
                } else {
                    const float* src = &g_h[layer][pprev][0][0];
                    const int koff = k - Kin;
                    #pragma unroll
                    for (int p = 0; p < 16; ++p) {
                        const int b = p * 4 + lr0;
                        As[lkk * PAD + b] = __ldcg(&src[b * HH + koff]);
                    }
                }
                // ---- stage W tile: entry (k, u', gate) at [k][u'*4+gate] ----
                #pragma unroll
                for (int p = 0; p < 16; ++p) {
                    const int jc   = p * 4 + lr0;      // 0..63
                    const int gate = jc >> 4;
                    const int up   = jc & 15;
                    Ws[lkk * PAD + up * 4 + gate] =
                        Wl[(size_t)(gate * HH + u0 + up) * fanin + k];
                }
                __syncthreads();

                #pragma unroll 16
                for (int kk = 0; kk < KT; ++kk) {
                    const float4 a  = *(const float4*)(As + kk * PAD + tr * 4);
                    const float4 wv = *(const float4*)(Ws + kk * PAD + tc * 4);
                    acc[0][0] += a.x * wv.x; acc[0][1] += a.x * wv.y;
                    acc[0][2] += a.x * wv.z; acc[0][3] += a.x * wv.w;
                    acc[1][0] += a.y * wv.x; acc[1][1] += a.y * wv.y;
                    acc[1][2] += a.y * wv.z; acc[1][3] += a.y * wv.w;
                    acc[2][0] += a.z * wv.x; acc[2][1] += a.z * wv.y;
                    acc[2][2] += a.z * wv.z; acc[2][3] += a.z * wv.w;
                    acc[3][0] += a.w * wv.x; acc[3][1] += a.w * wv.y;
                    acc[3][2] += a.w * wv.z; acc[3][3] += a.w * wv.w;
                }
                __syncthreads();
            }

            // ---- LSTM cell update (thread-local: owns (b, u) pairs) ----
            #pragma unroll
            for (int r = 0; r < 4; ++r) {
                const int b = tr * 4 + r;
                const int u = u0 + tc;
                const float zi = acc[r][0], zf = acc[r][1], zg = acc[r][2], zo = acc[r][3];
                const float si = 1.0f / (1.0f + __expf(-zi));
                const float sf = 1.0f / (1.0f + __expf(-zf));
                const float so = 1.0f / (1.0f + __expf(-zo));
                const float tg = tanhf(zg);
                const float c  = sf * g_c[layer][b][u] + si * tg;
                g_c[layer][b][u] = c;
                const float h = so * tanhf(c);
                g_h[layer][pcur][b][u] = h;
                if (layer == 3) g_h3[((size_t)b * SS + t) * HH + u] = h;
            }
        }
        gridbar(lgen);
    }

    // ---------------- Phase 2: LayerNorm + output projection ----------------
    float* As3 = sm;                         // [512][PAD] normalized h, k-major
    float* Ws3 = sm + 512 * PAD;             // [64][PAD]  Wo tile
    float* red = sm + 512 * PAD + 64 * PAD;  // reduce scratch (18 floats)
    const int lane = tid & 31, wrp = tid >> 5;

    for (int i = 0; i < 4; ++i) {
        const int base_row = bx * 256 + i * 64;   // 128 blocks * 4 * 64 = 32768 rows

        // LN 64 rows into As3 (transposed [k][row])
        for (int rr = 0; rr < 64; ++rr) {
            const size_t row = (size_t)base_row + rr;
            const float v0 = __ldcg(&g_h3[row * HH + tid]);
            const float v1 = __ldcg(&g_h3[row * HH + tid + 256]);
            float s = v0 + v1, s2 = v0 * v0 + v1 * v1;
            #pragma unroll
            for (int off = 16; off > 0; off >>= 1) {
                s  += __shfl_down_sync(0xffffffffu, s,  off);
                s2 += __shfl_down_sync(0xffffffffu, s2, off);
            }
            if (lane == 0) { red[wrp] = s; red[8 + wrp] = s2; }
            __syncthreads();
            if (tid == 0) {
                float S1 = 0.f, S2 = 0.f;
                for (int j = 0; j < 8; ++j) { S1 += red[j]; S2 += red[8 + j]; }
                const float mu  = S1 * (1.0f / 512.0f);
                const float var = S2 * (1.0f / 512.0f) - mu * mu;
                red[16] = mu;
                red[17] = rsqrtf(var + 1e-5f);
            }
            __syncthreads();
            const float mu = red[16], rstd = red[17];
            As3[tid * PAD + rr]         = (v0 - mu) * rstd * lng[tid]       + lnb[tid];
            As3[(tid + 256) * PAD + rr] = (v1 - mu) * rstd * lng[tid + 256] + lnb[tid + 256];
            __syncthreads();
        }

        // GEMM: [64 rows x 64 dout], K = 512
        float acc[4][4];
        #pragma unroll
        for (int r = 0; r < 4; ++r)
            #pragma unroll
            for (int g = 0; g < 4; ++g) acc[r][g] = 0.0f;

        for (int ch = 0; ch < 8; ++ch) {
            #pragma unroll
            for (int p = 0; p < 16; ++p) {
                const int jc = p * 4 + lr0;      // d index 0..63
                Ws3[lkk * PAD + (jc & 15) * 4 + (jc >> 4)] =
                    Wo[(size_t)jc * HH + ch * 64 + lkk];
            }
            __syncthreads();
            #pragma unroll 16
            for (int kk = 0; kk < 64; ++kk) {
                const float4 a  = *(const float4*)(As3 + (ch * 64 + kk) * PAD + tr * 4);
                const float4 wv = *(const float4*)(Ws3 + kk * PAD + tc * 4);
                acc[0][0] += a.x * wv.x; acc[0][1] += a.x * wv.y;
                acc[0][2] += a.x * wv.z; acc[0][3] += a.x * wv.w;
                acc[1][0] += a.y * wv.x; acc[1][1] += a.y * wv.y;
                acc[1][2] += a.y * wv.z; acc[1][3] += a.y * wv.w;
                acc[2][0] += a.z * wv.x; acc[2][1] += a.z * wv.y;
                acc[2][2] += a.z * wv.z; acc[2][3] += a.z * wv.w;
                acc[3][0] += a.w * wv.x; acc[3][1] += a.w * wv.y;
                acc[3][2] += a.w * wv.z; acc[3][3] += a.w * wv.w;
            }
            __syncthreads();
        }

        #pragma unroll
        for (int r = 0; r < 4; ++r) {
            const size_t row = (size_t)base_row + tr * 4 + r;
            #pragma unroll
            for (int g = 0; g < 4; ++g) {
                const int d = g * 16 + tc;
                out[row * DOUT + d] = acc[r][g] + bo[d];
            }
        }
        __syncthreads();
    }
}

extern "C" void kernel_launch(void* const* d_in, const int* in_sizes, int n_in,
                              void* d_out, int out_size) {
    const float* x   = (const float*)d_in[0];
    const float* W0  = (const float*)d_in[1];
    const float* b0  = (const float*)d_in[2];
    const float* W1  = (const float*)d_in[3];
    const float* b1  = (const float*)d_in[4];
    const float* W2  = (const float*)d_in[5];
    const float* b2  = (const float*)d_in[6];
    const float* W3  = (const float*)d_in[7];
    const float* b3  = (const float*)d_in[8];
    const float* lng = (const float*)d_in[9];
    const float* lnb = (const float*)d_in[10];
    const float* Wo  = (const float*)d_in[11];
    const float* bo  = (const float*)d_in[12];
    float* out = (float*)d_out;

    cudaFuncSetAttribute(lstm_persistent_kernel,
                         cudaFuncAttributeMaxDynamicSharedMemorySize, SMEM_BYTES);
    lstm_persistent_kernel<<<NB, NT, SMEM_BYTES>>>(
        x, W0, b0, W1, b1, W2, b2, W3, b3, lng, lnb, Wo, bo, out);
}

// round 5
// speedup vs baseline: 2.6504x; 2.6412x over previous
#include <cuda_runtime.h>
#include <cstdint>
#include <math.h>

// ---------------- problem constants ----------------
#define BB   64
#define SS   512
#define DIN  64
#define HH   512
#define NLAY 4
#define DOUT 64

// ---------------- config ----------------
#define NB   128         // 32 blocks per layer
#define NT   256
#define BPL  32          // blocks per layer
#define UPB  16          // hidden units per block (64 gate rows)
#define KC   64          // K elements per chunk

// smem layout (phase 1)
#define APITCH    72                  // ushorts per row (144B, conflict-free)
#define PLANE_USH (64 * APITCH)       // 4608 ushorts = 9216 B
#define BUF_USH   (4 * PLANE_USH)     // Ahi, Alo, Bhi, Blo
#define DS_OFF_F  ((2 * BUF_USH * 2) / 4)   // float index of D staging (byte 73728)
#define DPITCH    68
#define PAD       68
#define SMEM_BYTES 156800             // phase-2 requirement dominates

// ---------------- persistent device state ----------------
__device__ unsigned short g_Whi[NLAY][2048][1024];   // pre-split weights, block-row order
__device__ unsigned short g_Wlo[NLAY][2048][1024];
__device__ unsigned short g_acthi[NLAY][2][BB][1024]; // per-layer B operand planes (bf16 hi)
__device__ unsigned short g_actlo[NLAY][2][BB][1024]; // (bf16 lo)
__device__ float g_h3[(size_t)BB * SS * HH];          // layer-3 h for phase 2
__device__ int g_cnt[NLAY];                           // per-layer wave progress
__device__ unsigned int g_arrive = 0;
__device__ unsigned int g_gen    = 0;

// ---------------- helpers ----------------
__device__ __forceinline__ unsigned short bf16rn(float v) {
    uint32_t u = __float_as_uint(v);
    uint32_t r = u + 0x7FFFu + ((u >> 16) & 1u);
    return (unsigned short)(r >> 16);
}
__device__ __forceinline__ void split2(float v, unsigned short& h, unsigned short& l) {
    h = bf16rn(v);
    float hf = __uint_as_float((uint32_t)h << 16);
    l = bf16rn(v - hf);
}
__device__ __forceinline__ float fsig(float x)   { return __fdividef(1.0f, 1.0f + __expf(-x)); }
__device__ __forceinline__ float ftanh_(float x) { return __fdividef(2.0f, 1.0f + __expf(-2.0f * x)) - 1.0f; }

__device__ __forceinline__ void poll_ge(int* p, int v) {
    int x;
    while (true) {
        asm volatile("ld.global.acquire.gpu.b32 %0, [%1];" : "=r"(x) : "l"(p) : "memory");
        if (x >= v) return;
        __nanosleep(64);
    }
}

__device__ __forceinline__ void mma_bf16(float* c, const uint32_t* a, const uint32_t* b) {
    asm volatile(
        "mma.sync.aligned.m16n8k16.row.col.f32.bf16.bf16.f32 "
        "{%0,%1,%2,%3}, {%4,%5,%6,%7}, {%8,%9}, {%0,%1,%2,%3};"
        : "+f"(c[0]), "+f"(c[1]), "+f"(c[2]), "+f"(c[3])
        : "r"(a[0]), "r"(a[1]), "r"(a[2]), "r"(a[3]), "r"(b[0]), "r"(b[1]));
}

__device__ __forceinline__ void gridbar(unsigned int& lgen) {
    __syncthreads();
    __threadfence();
    if (threadIdx.x == 0) {
        unsigned int old = atomicAdd(&g_arrive, 1u);
        if (((old + 1u) % NB) == 0u) {
            atomicAdd(&g_gen, 1u);
        } else {
            while (*((volatile unsigned int*)&g_gen) < lgen + 1u) { __nanosleep(32); }
        }
    }
    lgen += 1u;
    __syncthreads();
    __threadfence();
}

// ---- staging ----
__device__ __forceinline__ void stage_A(unsigned short* smu, int buf, int ch, int layer, int blk) {
    unsigned short* Ah = smu + buf * BUF_USH;
    unsigned short* Al = Ah + PLANE_USH;
    const int tid = threadIdx.x;
    const int k0 = ch * KC;
    #pragma unroll
    for (int j = 0; j < 2; ++j) {
        const int idx = tid + 256 * j, row = idx >> 3, q = idx & 7;
        uint4 vh = __ldg((const uint4*)&g_Whi[layer][blk * 64 + row][k0 + q * 8]);
        uint4 vl = __ldg((const uint4*)&g_Wlo[layer][blk * 64 + row][k0 + q * 8]);
        *(uint4*)(Ah + row * APITCH + q * 8) = vh;
        *(uint4*)(Al + row * APITCH + q * 8) = vl;
    }
}
__device__ __forceinline__ void stage_Bact(unsigned short* smu, int buf, int ch, int layer, int t, int Kin) {
    unsigned short* Bh = smu + buf * BUF_USH + 2 * PLANE_USH;
    unsigned short* Bl = Bh + PLANE_USH;
    const int tid = threadIdx.x;
    const int k0 = ch * KC;
    const int slot = (k0 < Kin) ? (t & 1) : ((t & 1) ^ 1);
    #pragma unroll
    for (int j = 0; j < 2; ++j) {
        const int idx = tid + 256 * j, n = idx >> 3, q = idx & 7;
        uint4 vh = __ldcg((const uint4*)&g_acthi[layer][slot][n][k0 + q * 8]);
        uint4 vl = __ldcg((const uint4*)&g_actlo[layer][slot][n][k0 + q * 8]);
        *(uint4*)(Bh + n * APITCH + q * 8) = vh;
        *(uint4*)(Bl + n * APITCH + q * 8) = vl;
    }
}
__device__ __forceinline__ void stage_x(unsigned short* smu, int buf, int t, const float* __restrict__ x) {
    unsigned short* Bh = smu + buf * BUF_USH + 2 * PLANE_USH;
    unsigned short* Bl = Bh + PLANE_USH;
    const int tid = threadIdx.x;
    #pragma unroll
    for (int j = 0; j < 4; ++j) {
        const int idx = tid + 256 * j;
        const int n = idx >> 4, q4 = idx & 15;
        float4 v = __ldg((const float4*)&x[((size_t)n * SS + t) * DIN + q4 * 4]);
        unsigned short h0, l0, h1, l1, h2, l2, h3, l3;
        split2(v.x, h0, l0); split2(v.y, h1, l1); split2(v.z, h2, l2); split2(v.w, h3, l3);
        *(uint2*)(Bh + n * APITCH + q4 * 4) =
            make_uint2((uint32_t)h0 | ((uint32_t)h1 << 16), (uint32_t)h2 | ((uint32_t)h3 << 16));
        *(uint2*)(Bl + n * APITCH + q4 * 4) =
            make_uint2((uint32_t)l0 | ((uint32_t)l1 << 16), (uint32_t)l2 | ((uint32_t)l3 << 16));
    }
}

__global__ void __launch_bounds__(NT, 1) lstm_mma_kernel(
    const float* __restrict__ x,
    const float* __restrict__ W0, const float* __restrict__ b0,
    const float* __restrict__ W1, const float* __restrict__ b1,
    const float* __restrict__ W2, const float* __restrict__ b2,
    const float* __restrict__ W3, const float* __restrict__ b3,
    const float* __restrict__ lng, const float* __restrict__ lnb,
    const float* __restrict__ Wo,  const float* __restrict__ bo,
    float* __restrict__ out)
{
    extern __shared__ char smc[];
    unsigned short* smu = (unsigned short*)smc;
    float* smf = (float*)smc;
    const int tid = threadIdx.x;
    const int bx  = blockIdx.x;
    unsigned int lgen = *((volatile unsigned int*)&g_gen);

    const float* Wsrc[4] = {W0, W1, W2, W3};
    const float* bsrc[4] = {b0, b1, b2, b3};

    // ---------------- phase 0: reset counters, zero act planes, split weights ----
    if (bx == 0 && tid < 4) g_cnt[tid] = 0;
    {
        uint4 z = make_uint4(0, 0, 0, 0);
        uint4* ph = (uint4*)&g_acthi[0][0][0][0];
        uint4* pl = (uint4*)&g_actlo[0][0][0][0];
        const int n16 = NLAY * 2 * BB * 1024 * 2 / 16;   // uint4 count per array
        for (int i = bx * NT + tid; i < n16; i += NB * NT) { ph[i] = z; pl[i] = z; }
    }
    {
        // each block reorders+splits 64 weight rows
        for (int rr = 0; rr < 64; ++rr) {
            const int gr = bx * 64 + rr;
            const int l = gr >> 11, r = gr & 2047;
            const int blk2 = r >> 6, rloc = r & 63, iu = rloc >> 2, g = rloc & 3;
            const int fanin = (l == 0) ? (DIN + HH) : (2 * HH);
            const float* src = Wsrc[l] + (size_t)(g * HH + blk2 * UPB + iu) * fanin;
            const int k = tid * 4;
            if (k < fanin) {
                float4 v = __ldg((const float4*)(src + k));
                unsigned short h0, l0, h1, l1, h2, l2, h3, l3;
                split2(v.x, h0, l0); split2(v.y, h1, l1);
                split2(v.z, h2, l2); split2(v.w, h3, l3);
                *(uint2*)&g_Whi[l][r][k] =
                    make_uint2((uint32_t)h0 | ((uint32_t)h1 << 16), (uint32_t)h2 | ((uint32_t)h3 << 16));
                *(uint2*)&g_Wlo[l][r][k] =
                    make_uint2((uint32_t)l0 | ((uint32_t)l1 << 16), (uint32_t)l2 | ((uint32_t)l3 << 16));
            }
        }
    }
    gridbar(lgen);

    // ---------------- phase 1: free-running wavefront LSTM on mma.sync ----------
    const int layer = bx >> 5;
    const int blk   = bx & 31;
    const int u0    = blk * UPB;
    const float* bl = bsrc[layer];
    const int fanin = (layer == 0) ? (DIN + HH) : (2 * HH);
    const int Kin   = (layer == 0) ? DIN : HH;
    const int nch   = fanin / KC;          // 9 or 16

    const int lane = tid & 31, wid = tid >> 5;
    const int wm = wid & 3, wn = wid >> 2;   // 4 x 2 warp grid
    const int fr = lane >> 2;                // fragment row
    const int fc = (lane & 3) * 2;           // fragment k/col offset

    const int eu  = tid >> 4;                // epilogue unit 0..15
    const int eb0 = (tid & 15) * 4;          // epilogue batch base
    const float bzi = __ldg(&bl[0 * HH + u0 + eu]);
    const float bzf = __ldg(&bl[1 * HH + u0 + eu]);
    const float bzg = __ldg(&bl[2 * HH + u0 + eu]);
    const float bzo = __ldg(&bl[3 * HH + u0 + eu]);
    float c_st[4] = {0.f, 0.f, 0.f, 0.f};

    float* Ds = smf + DS_OFF_F;
    const int ar0 = wm * 16 + fr;

    for (int t = 0; t < SS; ++t) {
        if (tid == 0) {
            if (t > 0)               poll_ge(&g_cnt[layer],     BPL * t);
            if (layer > 0)           poll_ge(&g_cnt[layer - 1], BPL * (t + 1));
            if (layer < 3 && t >= 1) poll_ge(&g_cnt[layer + 1], BPL * (t - 1));
        }
        __syncthreads();

        stage_A(smu, 0, 0, layer, blk);
        if (layer == 0) stage_x(smu, 0, t, x);
        else            stage_Bact(smu, 0, 0, layer, t, Kin);
        __syncthreads();

        float acc[4][4];
        #pragma unroll
        for (int a = 0; a < 4; ++a) { acc[a][0] = 0.f; acc[a][1] = 0.f; acc[a][2] = 0.f; acc[a][3] = 0.f; }

        for (int ch = 0; ch < nch; ++ch) {
            const int buf = ch & 1;
            const bool hv = (ch + 1 < nch);
            uint4 rAh[2], rAl[2], rBh[2], rBl[2];
            if (hv) {
                const int k0n = (ch + 1) * KC;
                #pragma unroll
                for (int j = 0; j < 2; ++j) {
                    const int idx = tid + 256 * j, row = idx >> 3, q = idx & 7;
                    rAh[j] = __ldg((const uint4*)&g_Whi[layer][blk * 64 + row][k0n + q * 8]);
                    rAl[j] = __ldg((const uint4*)&g_Wlo[layer][blk * 64 + row][k0n + q * 8]);
                }
                const int slot = (k0n < Kin) ? (t & 1) : ((t & 1) ^ 1);
                #pragma unroll
                for (int j = 0; j < 2; ++j) {
                    const int idx = tid + 256 * j, n = idx >> 3, q = idx & 7;
                    rBh[j] = __ldcg((const uint4*)&g_acthi[layer][slot][n][k0n + q * 8]);
                    rBl[j] = __ldcg((const uint4*)&g_actlo[layer][slot][n][k0n + q * 8]);
                }
            }

            const unsigned short* Ah = smu + buf * BUF_USH;
            const unsigned short* Al = Ah + PLANE_USH;
            const unsigned short* Bh = Al + PLANE_USH;
            const unsigned short* Bl = Bh + PLANE_USH;

            #pragma unroll
            for (int ks = 0; ks < 4; ++ks) {
                const int kb = ks * 16 + fc;
                uint32_t ah[4], al[4];
                ah[0] = *(const uint32_t*)(Ah + ar0 * APITCH + kb);
                ah[1] = *(const uint32_t*)(Ah + (ar0 + 8) * APITCH + kb);
                ah[2] = *(const uint32_t*)(Ah + ar0 * APITCH + kb + 8);
                ah[3] = *(const uint32_t*)(Ah + (ar0 + 8) * APITCH + kb + 8);
                al[0] = *(const uint32_t*)(Al + ar0 * APITCH + kb);
                al[1] = *(const uint32_t*)(Al + (ar0 + 8) * APITCH + kb);
                al[2] = *(const uint32_t*)(Al + ar0 * APITCH + kb + 8);
                al[3] = *(const uint32_t*)(Al + (ar0 + 8) * APITCH + kb + 8);
                #pragma unroll
                for (int tn = 0; tn < 4; ++tn) {
                    const int n0 = wn * 32 + tn * 8 + fr;
                    uint32_t bh[2], bl2[2];
                    bh[0]  = *(const uint32_t*)(Bh + n0 * APITCH + kb);
                    bh[1]  = *(const uint32_t*)(Bh + n0 * APITCH + kb + 8);
                    bl2[0] = *(const uint32_t*)(Bl + n0 * APITCH + kb);
                    bl2[1] = *(const uint32_t*)(Bl + n0 * APITCH + kb + 8);
                    mma_bf16(acc[tn], ah, bh);
                    mma_bf16(acc[tn], ah, bl2);
                    mma_bf16(acc[tn], al, bh);
                }
            }

            if (hv) {
                unsigned short* Dh = smu + (buf ^ 1) * BUF_USH;
                #pragma unroll
                for (int j = 0; j < 2; ++j) {
                    const int idx = tid + 256 * j, row = idx >> 3, q = idx & 7;
                    *(uint4*)(Dh + row * APITCH + q * 8)                 = rAh[j];
                    *(uint4*)(Dh + PLANE_USH + row * APITCH + q * 8)     = rAl[j];
                    *(uint4*)(Dh + 2 * PLANE_USH + row * APITCH + q * 8) = rBh[j];
                    *(uint4*)(Dh + 3 * PLANE_USH + row * APITCH + q * 8) = rBl[j];
                }
            }
            __syncthreads();
        }

        // stage D to smem
        #pragma unroll
        for (int tn = 0; tn < 4; ++tn) {
            const int col = wn * 32 + tn * 8 + fc;
            *(float2*)&Ds[ar0 * DPITCH + col]       = make_float2(acc[tn][0], acc[tn][1]);
            *(float2*)&Ds[(ar0 + 8) * DPITCH + col] = make_float2(acc[tn][2], acc[tn][3]);
        }
        __syncthreads();

        // gates + h writes (thread owns (eu, 4 batches))
        const int slot_w = t & 1;
        #pragma unroll
        for (int j = 0; j < 4; ++j) {
            const int b = eb0 + j;
            const float zi = Ds[(eu * 4 + 0) * DPITCH + b] + bzi;
            const float zf = Ds[(eu * 4 + 1) * DPITCH + b] + bzf;
            const float zg = Ds[(eu * 4 + 2) * DPITCH + b] + bzg;
            const float zo = Ds[(eu * 4 + 3) * DPITCH + b] + bzo;
            const float c = fsig(zf) * c_st[j] + fsig(zi) * ftanh_(zg);
            c_st[j] = c;
            const float h = fsig(zo) * ftanh_(c);
            unsigned short hh, hl;
            split2(h, hh, hl);
            g_acthi[layer][slot_w][b][Kin + u0 + eu] = hh;   // own recurrence region
            g_actlo[layer][slot_w][b][Kin + u0 + eu] = hl;
            if (layer < 3) {
                g_acthi[layer + 1][slot_w][b][u0 + eu] = hh; // next layer's input region
                g_actlo[layer + 1][slot_w][b][u0 + eu] = hl;
            } else {
                g_h3[((size_t)b * SS + t) * HH + u0 + eu] = h;
            }
        }
        __syncthreads();
        if (tid == 0) {
            __threadfence();
            atomicAdd(&g_cnt[layer], 1);
        }
    }

    // ---------------- phase 2: LayerNorm + output projection --------------------
    if (tid == 0) poll_ge(&g_cnt[3], BPL * SS);
    __syncthreads();

    float* As3 = smf;
    float* Ws3 = smf + 512 * PAD;
    float* red = smf + 512 * PAD + 64 * PAD;
    const int wrp = tid >> 5;
    const int tc  = tid & 15, tr = tid >> 4;
    const int lkk = tid & 63, lr0 = tid >> 6;

    for (int i = 0; i < 4; ++i) {
        const int base_row = bx * 256 + i * 64;

        for (int rr = 0; rr < 64; ++rr) {
            const size_t row = (size_t)base_row + rr;
            const float v0 = __ldcg(&g_h3[row * HH + tid]);
            const float v1 = __ldcg(&g_h3[row * HH + tid + 256]);
            float s = v0 + v1, s2 = v0 * v0 + v1 * v1;
            #pragma unroll
            for (int off = 16; off > 0; off >>= 1) {
                s  += __shfl_down_sync(0xffffffffu, s,  off);
                s2 += __shfl_down_sync(0xffffffffu, s2, off);
            }
            if (lane == 0) { red[wrp] = s; red[8 + wrp] = s2; }
            __syncthreads();
            if (tid == 0) {
                float S1 = 0.f, S2 = 0.f;
                for (int jj = 0; jj < 8; ++jj) { S1 += red[jj]; S2 += red[8 + jj]; }
                const float mu  = S1 * (1.0f / 512.0f);
                const float var = S2 * (1.0f / 512.0f) - mu * mu;
                red[16] = mu;
                red[17] = rsqrtf(var + 1e-5f);
            }
            __syncthreads();
            const float mu = red[16], rstd = red[17];
            As3[tid * PAD + rr]         = (v0 - mu) * rstd * lng[tid]       + lnb[tid];
            As3[(tid + 256) * PAD + rr] = (v1 - mu) * rstd * lng[tid + 256] + lnb[tid + 256];
            __syncthreads();
        }

        float acc[4][4];
        #pragma unroll
        for (int r = 0; r < 4; ++r)
            #pragma unroll
            for (int g = 0; g < 4; ++g) acc[r][g] = 0.0f;

        for (int ch = 0; ch < 8; ++ch) {
            #pragma unroll
            for (int p = 0; p < 16; ++p) {
                const int jc = p * 4 + lr0;
                Ws3[lkk * PAD + (jc & 15) * 4 + (jc >> 4)] =
                    Wo[(size_t)jc * HH + ch * 64 + lkk];
            }
            __syncthreads();
            #pragma unroll 16
            for (int kk = 0; kk < 64; ++kk) {
                const float4 a  = *(const float4*)(As3 + (ch * 64 + kk) * PAD + tr * 4);
                const float4 wv = *(const float4*)(Ws3 + kk * PAD + tc * 4);
                acc[0][0] += a.x * wv.x; acc[0][1] += a.x * wv.y;
                acc[0][2] += a.x * wv.z; acc[0][3] += a.x * wv.w;
                acc[1][0] += a.y * wv.x; acc[1][1] += a.y * wv.y;
                acc[1][2] += a.y * wv.z; acc[1][3] += a.y * wv.w;
                acc[2][0] += a.z * wv.x; acc[2][1] += a.z * wv.y;
                acc[2][2] += a.z * wv.z; acc[2][3] += a.z * wv.w;
                acc[3][0] += a.w * wv.x; acc[3][1] += a.w * wv.y;
                acc[3][2] += a.w * wv.z; acc[3][3] += a.w * wv.w;
            }
            __syncthreads();
        }

        #pragma unroll
        for (int r = 0; r < 4; ++r) {
            const size_t row = (size_t)base_row + tr * 4 + r;
            #pragma unroll
            for (int g = 0; g < 4; ++g) {
                const int d = g * 16 + tc;
                out[row * DOUT + d] = acc[r][g] + bo[d];
            }
        }
        __syncthreads();
    }
}

extern "C" void kernel_launch(void* const* d_in, const int* in_sizes, int n_in,
                              void* d_out, int out_size) {
    const float* x   = (const float*)d_in[0];
    const float* W0  = (const float*)d_in[1];
    const float* b0  = (const float*)d_in[2];
    const float* W1  = (const float*)d_in[3];
    const float* b1  = (const float*)d_in[4];
    const float* W2  = (const float*)d_in[5];
    const float* b2  = (const float*)d_in[6];
    const float* W3  = (const float*)d_in[7];
    const float* b3  = (const float*)d_in[8];
    const float* lng = (const float*)d_in[9];
    const float* lnb = (const float*)d_in[10];
    const float* Wo  = (const float*)d_in[11];
    const float* bo  = (const float*)d_in[12];
    float* out = (float*)d_out;

    cudaFuncSetAttribute(lstm_mma_kernel,
                         cudaFuncAttributeMaxDynamicSharedMemorySize, SMEM_BYTES);
    lstm_mma_kernel<<<NB, NT, SMEM_BYTES>>>(
        x, W0, b0, W1, b1, W2, b2, W3, b3, lng, lnb, Wo, bo, out);
}